// round 1
// baseline (speedup 1.0000x reference)
#include <cuda_runtime.h>

// Problem constants
#define T_STEPS 200
#define BATCH   256
#define RES     2048
#define INPD    3
#define OUTD    2
#define BETA    0.9f
#define THRESH  1.0f

#define SPK_ELEMS ((size_t)T_STEPS * BATCH * RES)

// Membrane potential state (zeroed at the start of every kernel_launch replay)
__device__ float g_V[BATCH * RES];

// ---------------------------------------------------------------------------
// init: zero V
// ---------------------------------------------------------------------------
__global__ void init_kernel() {
    int idx = blockIdx.x * blockDim.x + threadIdx.x;
    int stride = gridDim.x * blockDim.x;
    for (int i = idx; i < BATCH * RES; i += stride) g_V[i] = 0.0f;
}

// ---------------------------------------------------------------------------
// step: Y = S_{t-1} @ W  (fp32 SIMT GEMM), then fused neuron update:
//   y = BETA*V + x_t@Win^T + Y ;  s = (y>=1) ;  V = s ? 0 : y ;  out[t] = s
// S_{t-1} is read from the output spike slab at row t-1 (zeros for t==0).
// ---------------------------------------------------------------------------
#define BM 64
#define BN 64
#define BK 16

__global__ void __launch_bounds__(256, 1)
step_kernel(const float* __restrict__ W,
            const float* __restrict__ x,
            const float* __restrict__ Win,
            float* __restrict__ out,
            int t)
{
    __shared__ float As[BK][BM];   // S tile, stored k-major (transposed)
    __shared__ float Bs[BK][BN];   // W tile

    const int tid = threadIdx.x;
    const int tx  = tid & 15;      // 0..15 -> N direction
    const int ty  = tid >> 4;      // 0..15 -> M direction
    const int n0  = blockIdx.x * BN;
    const int m0  = blockIdx.y * BM;

    float acc[4][4] = {};

    if (t > 0) {
        const float* S = out + (size_t)(t - 1) * BATCH * RES;

        // global-load coordinates
        const int ar = tid >> 2;          // 0..63 : A row (batch)
        const int ac = (tid & 3) * 4;     // 0,4,8,12 : A col (k)
        const int br = tid >> 4;          // 0..15 : B row (k)
        const int bc = (tid & 15) * 4;    // 0..60 : B col

        for (int k0 = 0; k0 < RES; k0 += BK) {
            float4 av = *(const float4*)&S[(size_t)(m0 + ar) * RES + k0 + ac];
            As[ac + 0][ar] = av.x;
            As[ac + 1][ar] = av.y;
            As[ac + 2][ar] = av.z;
            As[ac + 3][ar] = av.w;
            *(float4*)&Bs[br][bc] =
                *(const float4*)&W[(size_t)(k0 + br) * RES + n0 + bc];
            __syncthreads();

            #pragma unroll
            for (int k = 0; k < BK; k++) {
                const float a0 = As[k][ty * 4 + 0];
                const float a1 = As[k][ty * 4 + 1];
                const float a2 = As[k][ty * 4 + 2];
                const float a3 = As[k][ty * 4 + 3];
                const float4 b4 = *(const float4*)&Bs[k][tx * 4];
                acc[0][0] = fmaf(a0, b4.x, acc[0][0]);
                acc[0][1] = fmaf(a0, b4.y, acc[0][1]);
                acc[0][2] = fmaf(a0, b4.z, acc[0][2]);
                acc[0][3] = fmaf(a0, b4.w, acc[0][3]);
                acc[1][0] = fmaf(a1, b4.x, acc[1][0]);
                acc[1][1] = fmaf(a1, b4.y, acc[1][1]);
                acc[1][2] = fmaf(a1, b4.z, acc[1][2]);
                acc[1][3] = fmaf(a1, b4.w, acc[1][3]);
                acc[2][0] = fmaf(a2, b4.x, acc[2][0]);
                acc[2][1] = fmaf(a2, b4.y, acc[2][1]);
                acc[2][2] = fmaf(a2, b4.z, acc[2][2]);
                acc[2][3] = fmaf(a2, b4.w, acc[2][3]);
                acc[3][0] = fmaf(a3, b4.x, acc[3][0]);
                acc[3][1] = fmaf(a3, b4.y, acc[3][1]);
                acc[3][2] = fmaf(a3, b4.z, acc[3][2]);
                acc[3][3] = fmaf(a3, b4.w, acc[3][3]);
            }
            __syncthreads();
        }
    }

    // ---- fused epilogue: leak + input injection + threshold + reset ----
    const float* xt   = x + (size_t)t * BATCH * INPD;
    float*       outT = out + (size_t)t * BATCH * RES;
    const int j0 = n0 + tx * 4;

    // Win rows for this thread's 4 output columns
    float wv[4][3];
    #pragma unroll
    for (int n = 0; n < 4; n++) {
        wv[n][0] = Win[(j0 + n) * 3 + 0];
        wv[n][1] = Win[(j0 + n) * 3 + 1];
        wv[n][2] = Win[(j0 + n) * 3 + 2];
    }

    #pragma unroll
    for (int m = 0; m < 4; m++) {
        const int b = m0 + ty * 4 + m;
        const float x0 = xt[b * 3 + 0];
        const float x1 = xt[b * 3 + 1];
        const float x2 = xt[b * 3 + 2];
        const size_t base = (size_t)b * RES + j0;

        float4 v = *(const float4*)&g_V[base];

        float inj[4];
        #pragma unroll
        for (int n = 0; n < 4; n++)
            inj[n] = x0 * wv[n][0] + x1 * wv[n][1] + x2 * wv[n][2];

        float y0 = BETA * v.x + inj[0] + acc[m][0];
        float y1 = BETA * v.y + inj[1] + acc[m][1];
        float y2 = BETA * v.z + inj[2] + acc[m][2];
        float y3 = BETA * v.w + inj[3] + acc[m][3];

        float4 s;
        s.x = (y0 >= THRESH) ? 1.0f : 0.0f;
        s.y = (y1 >= THRESH) ? 1.0f : 0.0f;
        s.z = (y2 >= THRESH) ? 1.0f : 0.0f;
        s.w = (y3 >= THRESH) ? 1.0f : 0.0f;

        v.x = (y0 >= THRESH) ? 0.0f : y0;
        v.y = (y1 >= THRESH) ? 0.0f : y1;
        v.z = (y2 >= THRESH) ? 0.0f : y2;
        v.w = (y3 >= THRESH) ? 0.0f : y3;

        *(float4*)&g_V[base] = v;
        *(float4*)&outT[base] = s;
    }
}

// ---------------------------------------------------------------------------
// logits: spk_avg = mean(spk_rec[-10:]) ; logits = spk_avg @ Wout^T
// one block per batch element
// ---------------------------------------------------------------------------
__global__ void __launch_bounds__(256)
logits_kernel(const float* __restrict__ spk,
              const float* __restrict__ Wout,
              float* __restrict__ logits)
{
    const int b = blockIdx.x;
    const int tid = threadIdx.x;
    float p0 = 0.0f, p1 = 0.0f;

    for (int r = tid; r < RES; r += 256) {
        float s = 0.0f;
        #pragma unroll
        for (int tt = 0; tt < 10; tt++)
            s += spk[((size_t)(T_STEPS - 10 + tt) * BATCH + b) * RES + r];
        s *= 0.1f;
        p0 = fmaf(s, Wout[r], p0);
        p1 = fmaf(s, Wout[RES + r], p1);
    }

    __shared__ float sh0[256];
    __shared__ float sh1[256];
    sh0[tid] = p0;
    sh1[tid] = p1;
    __syncthreads();
    for (int off = 128; off > 0; off >>= 1) {
        if (tid < off) {
            sh0[tid] += sh0[tid + off];
            sh1[tid] += sh1[tid + off];
        }
        __syncthreads();
    }
    if (tid == 0) {
        logits[b * OUTD + 0] = sh0[0];
        logits[b * OUTD + 1] = sh1[0];
    }
}

// ---------------------------------------------------------------------------
extern "C" void kernel_launch(void* const* d_in, const int* in_sizes, int n_in,
                              void* d_out, int out_size)
{
    const float* x    = (const float*)d_in[0];  // [200, 256, 3]
    const float* W    = (const float*)d_in[1];  // [2048, 2048]
    const float* Win  = (const float*)d_in[2];  // [2048, 3]
    const float* Wout = (const float*)d_in[3];  // [2, 2048]
    float* out = (float*)d_out;                 // [200*256*2048] spk | [256*2] logits

    init_kernel<<<512, 256>>>();

    dim3 grid(RES / BN, BATCH / BM);  // 32 x 4 = 128 blocks
    for (int t = 0; t < T_STEPS; t++) {
        step_kernel<<<grid, 256>>>(W, x, Win, out, t);
    }

    logits_kernel<<<BATCH, 256>>>(out, Wout, out + SPK_ELEMS);
}

// round 3
// speedup vs baseline: 2.6607x; 2.6607x over previous
#include <cuda_runtime.h>
#include <cuda_bf16.h>
#include <cstdint>

// ---------------- problem constants ----------------
#define T_STEPS 200
#define BATCH   256
#define RES     2048
#define OUTD    2
#define BETA    0.9f
#define THRESH  1.0f
#define SPK_ELEMS ((size_t)T_STEPS * BATCH * RES)
#define NSPLIT 3

// GEMM tiling: CTA 64(M) x 64(N), k-chunk 64, 256 threads (8 warps, 2x4),
// warp tile 32(M) x 16(N), mma.sync m16n8k16 bf16.
#define BM 64
#define BN 64
#define BK 64
#define KCHUNKS (RES / BK)              // 32
#define NJ (KCHUNKS * NSPLIT)           // 96 (chunk,split) stages
#define ROW_BYTES 4096                  // 2048 bf16 per row

// ---------------- device state ----------------
__device__ float         g_V[BATCH * RES];
__device__ __nv_bfloat16 g_S[2 * BATCH * RES];                    // spike double buffer
__device__ __nv_bfloat16 g_W3[(size_t)NSPLIT * RES * RES];        // split W, [s][n][k]

// ---------------- helpers ----------------
__device__ __forceinline__ uint32_t smem_u32(const void* p) {
    uint32_t a;
    asm("{ .reg .u64 t; cvta.to.shared.u64 t, %1; cvt.u32.u64 %0, t; }" : "=r"(a) : "l"(p));
    return a;
}

__device__ __forceinline__ void ldsm4(uint32_t* r, uint32_t addr) {
    asm volatile("ldmatrix.sync.aligned.m8n8.x4.shared.b16 {%0,%1,%2,%3}, [%4];"
                 : "=r"(r[0]), "=r"(r[1]), "=r"(r[2]), "=r"(r[3]) : "r"(addr));
}

__device__ __forceinline__ void mma16816(float* c, const uint32_t* a, uint32_t b0, uint32_t b1) {
    asm volatile("mma.sync.aligned.m16n8k16.row.col.f32.bf16.bf16.f32 "
                 "{%0,%1,%2,%3}, {%4,%5,%6,%7}, {%8,%9}, {%0,%1,%2,%3};"
                 : "+f"(c[0]), "+f"(c[1]), "+f"(c[2]), "+f"(c[3])
                 : "r"(a[0]), "r"(a[1]), "r"(a[2]), "r"(a[3]), "r"(b0), "r"(b1));
}

#define CP_COMMIT() asm volatile("cp.async.commit_group;" ::: "memory")
#define CP_WAIT1()  asm volatile("cp.async.wait_group 1;" ::: "memory")

// 64x64 bf16 tile (8KB): rows of 128B = 8 x 16B chunks, chunk ^= row%8 swizzle.
// 256 threads, 2 x 16B cp.async each.
__device__ __forceinline__ void load_tile256(uint32_t sbase, const char* g) {
    const int tid = threadIdx.x;
    #pragma unroll
    for (int i = 0; i < 2; i++) {
        int c = tid + i * 256;
        int row = c >> 3, ch = c & 7;
        uint32_t dst = sbase + row * 128 + ((ch ^ (row & 7)) << 4);
        const char* src = g + (size_t)row * ROW_BYTES + ch * 16;
        asm volatile("cp.async.cg.shared.global [%0], [%1], 16;" :: "r"(dst), "l"(src));
    }
}

// ---------------------------------------------------------------------------
__global__ void init_kernel() {
    int idx = blockIdx.x * blockDim.x + threadIdx.x;
    int stride = gridDim.x * blockDim.x;
    for (int i = idx; i < BATCH * RES; i += stride) g_V[i] = 0.0f;
}

// split+transpose W: g_W3[s][n][k] = bf16 split s of W[k][n]
__global__ void split_kernel(const float* __restrict__ W) {
    __shared__ float sh[32][33];
    const int k0 = blockIdx.x * 32;
    const int n0 = blockIdx.y * 32;
    const int tx = threadIdx.x;
    const int ty = threadIdx.y;
    #pragma unroll
    for (int i = ty; i < 32; i += 8)
        sh[i][tx] = W[(size_t)(k0 + i) * RES + n0 + tx];
    __syncthreads();
    #pragma unroll
    for (int i = ty; i < 32; i += 8) {
        float w = sh[tx][i];  // = W[k0+tx][n0+i]
        __nv_bfloat16 b0 = __float2bfloat16(w);
        float r1 = w - __bfloat162float(b0);
        __nv_bfloat16 b1 = __float2bfloat16(r1);
        float r2 = r1 - __bfloat162float(b1);
        __nv_bfloat16 b2 = __float2bfloat16(r2);
        size_t o = (size_t)(n0 + i) * RES + k0 + tx;
        g_W3[o]                         = b0;
        g_W3[(size_t)RES * RES + o]     = b1;
        g_W3[(size_t)2 * RES * RES + o] = b2;
    }
}

// ---------------------------------------------------------------------------
// step: Y = S_{t-1} @ (W0+W1+W2) via mma.sync bf16, fused LIF epilogue.
// ---------------------------------------------------------------------------
__global__ void __launch_bounds__(256)
step_kernel(const float* __restrict__ x,
            const float* __restrict__ Win,
            float* __restrict__ out,
            int t)
{
    __shared__ __nv_bfloat16 As[2][BM * BK];   // 2 x 8KB
    __shared__ __nv_bfloat16 Bs[3][BN * BK];   // 3 x 8KB
    __shared__ float sWin[BN * 3];

    const int tid  = threadIdx.x;
    const int lane = tid & 31;
    const int warp = tid >> 5;
    const int n0 = blockIdx.x * BN;
    const int m0 = blockIdx.y * BM;
    const int wm = warp >> 2;        // 0..1 -> m offset *32
    const int wn = warp & 3;         // 0..3 -> n offset *16
    const int grp  = lane >> 3;      // ldmatrix address group
    const int lrow = lane & 7;
    const int lr = lane >> 2;        // mma frag row
    const int lc = lane & 3;         // mma frag col pair

    for (int i = tid; i < BN * 3; i += 256) sWin[i] = Win[n0 * 3 + i];

    float acc[2][2][4];
    #pragma unroll
    for (int a = 0; a < 2; a++)
        #pragma unroll
        for (int b = 0; b < 2; b++)
            #pragma unroll
            for (int c = 0; c < 4; c++) acc[a][b][c] = 0.0f;

    if (t > 0) {
        const uint32_t sA0 = smem_u32(As);
        const uint32_t sB0 = smem_u32(Bs);
        const char* gA = (const char*)g_S
            + (size_t)((t + 1) & 1) * BATCH * RES * 2 + (size_t)m0 * ROW_BYTES;
        const char* gB = (const char*)g_W3 + (size_t)n0 * ROW_BYTES;
        const size_t SSTR = (size_t)RES * RES * 2;   // split stride (bytes)

        // preamble: stage 0 (A chunk0 + B(c0,s0)), stage 1 (B(c0,s1))
        load_tile256(sA0, gA);
        load_tile256(sB0, gB);
        CP_COMMIT();
        load_tile256(sB0 + 8192, gB + SSTR);
        CP_COMMIT();

        // ldmatrix per-thread row bases
        // A frag (mi): row = wm*32 + mi*16 + (grp&1)*8 + lrow ; k-half = grp>>1
        // B frag:      row = wn*16 + (grp>>1)*8 + lrow        ; k-half = grp&1
        const int rowA0 = wm * 32 + (grp & 1) * 8 + lrow;
        const int rowA1 = rowA0 + 16;
        const int rowB  = wn * 16 + (grp >> 1) * 8 + lrow;
        const uint32_t aOff0 = rowA0 * 128, aOff1 = rowA1 * 128, bOff = rowB * 128;
        const int a7_0 = rowA0 & 7, a7_1 = rowA1 & 7, b7 = rowB & 7;
        const int akh = grp >> 1, bkh = grp & 1;

        for (int j = 0; j < NJ; j++) {
            CP_WAIT1();
            __syncthreads();

            const int cc = j / 3;
            const uint32_t aT = sA0 + ((cc & 1) << 13);
            const uint32_t bT = sB0 + (j - cc * 3) * 8192;

            #pragma unroll
            for (int kk = 0; kk < 4; kk++) {
                uint32_t a0[4], a1[4], bb[4];
                ldsm4(a0, aT + aOff0 + ((((kk << 1) | akh) ^ a7_0) << 4));
                ldsm4(a1, aT + aOff1 + ((((kk << 1) | akh) ^ a7_1) << 4));
                ldsm4(bb, bT + bOff  + ((((kk << 1) | bkh) ^ b7)   << 4));
                // bb: {b0(nt0), b1(nt0), b0(nt1), b1(nt1)}
                mma16816(acc[0][0], a0, bb[0], bb[1]);
                mma16816(acc[0][1], a0, bb[2], bb[3]);
                mma16816(acc[1][0], a1, bb[0], bb[1]);
                mma16816(acc[1][1], a1, bb[2], bb[3]);
            }

            const int jn = j + 2;
            if (jn < NJ) {
                const int cn = jn / 3, sn = jn - cn * 3;
                load_tile256(sB0 + (jn % 3) * 8192, gB + (size_t)sn * SSTR + (size_t)cn * 128);
                if (sn == 0)
                    load_tile256(sA0 + ((cn & 1) << 13), gA + (size_t)cn * 128);
            }
            CP_COMMIT();
        }
    }

    __syncthreads();

    // ---- fused LIF epilogue ----
    const float* xt = x + (size_t)t * BATCH * 3;
    float*         outT = out + (size_t)t * BATCH * RES;
    __nv_bfloat16* Sw   = g_S + (size_t)(t & 1) * BATCH * RES;

    #pragma unroll
    for (int mi = 0; mi < 2; mi++) {
        #pragma unroll
        for (int r = 0; r < 2; r++) {
            const int b = m0 + wm * 32 + mi * 16 + r * 8 + lr;
            const float x0 = xt[b * 3 + 0];
            const float x1 = xt[b * 3 + 1];
            const float x2 = xt[b * 3 + 2];
            #pragma unroll
            for (int nt = 0; nt < 2; nt++) {
                const int nl = wn * 16 + nt * 8 + lc * 2;
                const size_t vi = (size_t)b * RES + n0 + nl;
                const float inj0 = x0 * sWin[nl * 3 + 0] + x1 * sWin[nl * 3 + 1] + x2 * sWin[nl * 3 + 2];
                const float inj1 = x0 * sWin[nl * 3 + 3] + x1 * sWin[nl * 3 + 4] + x2 * sWin[nl * 3 + 5];
                float2 v = *(float2*)&g_V[vi];
                const float y0 = BETA * v.x + inj0 + acc[mi][nt][r * 2 + 0];
                const float y1 = BETA * v.y + inj1 + acc[mi][nt][r * 2 + 1];
                const float s0 = (y0 >= THRESH) ? 1.0f : 0.0f;
                const float s1 = (y1 >= THRESH) ? 1.0f : 0.0f;
                v.x = (y0 >= THRESH) ? 0.0f : y0;
                v.y = (y1 >= THRESH) ? 0.0f : y1;
                *(float2*)&g_V[vi] = v;
                float2 sp; sp.x = s0; sp.y = s1;
                *(float2*)&outT[vi] = sp;
                __nv_bfloat162 sb;
                sb.x = __float2bfloat16(s0);
                sb.y = __float2bfloat16(s1);
                *(__nv_bfloat162*)&Sw[vi] = sb;
            }
        }
    }
}

// ---------------------------------------------------------------------------
__global__ void __launch_bounds__(256)
logits_kernel(const float* __restrict__ spk,
              const float* __restrict__ Wout,
              float* __restrict__ logits)
{
    const int b = blockIdx.x;
    const int tid = threadIdx.x;
    float p0 = 0.0f, p1 = 0.0f;
    for (int r = tid; r < RES; r += 256) {
        float s = 0.0f;
        #pragma unroll
        for (int tt = 0; tt < 10; tt++)
            s += spk[((size_t)(T_STEPS - 10 + tt) * BATCH + b) * RES + r];
        s *= 0.1f;
        p0 = fmaf(s, Wout[r], p0);
        p1 = fmaf(s, Wout[RES + r], p1);
    }
    __shared__ float sh0[256];
    __shared__ float sh1[256];
    sh0[tid] = p0; sh1[tid] = p1;
    __syncthreads();
    for (int off = 128; off > 0; off >>= 1) {
        if (tid < off) { sh0[tid] += sh0[tid + off]; sh1[tid] += sh1[tid + off]; }
        __syncthreads();
    }
    if (tid == 0) {
        logits[b * OUTD + 0] = sh0[0];
        logits[b * OUTD + 1] = sh1[0];
    }
}

// ---------------------------------------------------------------------------
extern "C" void kernel_launch(void* const* d_in, const int* in_sizes, int n_in,
                              void* d_out, int out_size)
{
    const float* x    = (const float*)d_in[0];  // [200, 256, 3]
    const float* W    = (const float*)d_in[1];  // [2048, 2048]
    const float* Win  = (const float*)d_in[2];  // [2048, 3]
    const float* Wout = (const float*)d_in[3];  // [2, 2048]
    float* out = (float*)d_out;                 // spk [200*256*2048] | logits [256*2]

    init_kernel<<<512, 256>>>();
    split_kernel<<<dim3(RES / 32, RES / 32), dim3(32, 8)>>>(W);

    dim3 grid(RES / BN, BATCH / BM);  // (32, 4) = 128 CTAs
    for (int t = 0; t < T_STEPS; t++) {
        step_kernel<<<grid, 256>>>(x, Win, out, t);
    }

    logits_kernel<<<BATCH, 256>>>(out, Wout, out + SPK_ELEMS);
}

// round 4
// speedup vs baseline: 4.4234x; 1.6625x over previous
#include <cuda_runtime.h>
#include <cuda_bf16.h>
#include <cstdint>

// ---------------- problem constants ----------------
#define T_STEPS 200
#define BATCH   256
#define RES     2048
#define OUTD    2
#define BETA    0.9f
#define THRESH  1.0f
#define SPK_ELEMS ((size_t)T_STEPS * BATCH * RES)
#define NSPLIT 3

// GEMM tiling: CTA 64(M) x 64(N), k-chunk 64, 256 threads (8 warps, 2x4),
// warp tile 32(M) x 16(N), mma.sync m16n8k16 bf16.
// Pipeline unit = one k-chunk: A tile (8KB) + 3 B split tiles (24KB) = 32KB.
// 4-stage ring = 128KB dynamic smem.
#define BM 64
#define BN 64
#define BK 64
#define KCHUNKS (RES / BK)              // 32
#define ROW_BYTES 4096                  // 2048 bf16 per row
#define STAGE_BYTES 32768
#define NSTAGE 4
#define SMEM_DYN (NSTAGE * STAGE_BYTES) // 131072

// ---------------- device state ----------------
__device__ float         g_V[BATCH * RES];
__device__ __nv_bfloat16 g_S[2 * BATCH * RES];                    // spike double buffer
__device__ __nv_bfloat16 g_W3[(size_t)NSPLIT * RES * RES];        // split W, [s][n][k]

// ---------------- helpers ----------------
__device__ __forceinline__ uint32_t smem_u32(const void* p) {
    uint32_t a;
    asm("{ .reg .u64 t; cvta.to.shared.u64 t, %1; cvt.u32.u64 %0, t; }" : "=r"(a) : "l"(p));
    return a;
}

__device__ __forceinline__ void ldsm4(uint32_t* r, uint32_t addr) {
    asm volatile("ldmatrix.sync.aligned.m8n8.x4.shared.b16 {%0,%1,%2,%3}, [%4];"
                 : "=r"(r[0]), "=r"(r[1]), "=r"(r[2]), "=r"(r[3]) : "r"(addr));
}

__device__ __forceinline__ void mma16816(float* c, const uint32_t* a, uint32_t b0, uint32_t b1) {
    asm volatile("mma.sync.aligned.m16n8k16.row.col.f32.bf16.bf16.f32 "
                 "{%0,%1,%2,%3}, {%4,%5,%6,%7}, {%8,%9}, {%0,%1,%2,%3};"
                 : "+f"(c[0]), "+f"(c[1]), "+f"(c[2]), "+f"(c[3])
                 : "r"(a[0]), "r"(a[1]), "r"(a[2]), "r"(a[3]), "r"(b0), "r"(b1));
}

#define CP_COMMIT() asm volatile("cp.async.commit_group;" ::: "memory")
#define CP_WAIT2()  asm volatile("cp.async.wait_group 2;" ::: "memory")

// 64x64 bf16 tile (8KB): rows of 128B = 8 x 16B chunks, chunk ^= row%8 swizzle.
// 256 threads, 2 x 16B cp.async each.
__device__ __forceinline__ void load_tile256(uint32_t sbase, const char* g) {
    const int tid = threadIdx.x;
    #pragma unroll
    for (int i = 0; i < 2; i++) {
        int c = tid + i * 256;
        int row = c >> 3, ch = c & 7;
        uint32_t dst = sbase + row * 128 + ((ch ^ (row & 7)) << 4);
        const char* src = g + (size_t)row * ROW_BYTES + ch * 16;
        asm volatile("cp.async.cg.shared.global [%0], [%1], 16;" :: "r"(dst), "l"(src));
    }
}

// load one k-chunk: A tile + 3 B split tiles into one stage
__device__ __forceinline__ void load_chunk(uint32_t stage, const char* gA, const char* gB,
                                           int chunk, size_t sstr) {
    load_tile256(stage, gA + (size_t)chunk * 128);
    #pragma unroll
    for (int s = 0; s < NSPLIT; s++)
        load_tile256(stage + 8192 + s * 8192, gB + (size_t)s * sstr + (size_t)chunk * 128);
}

// ---------------------------------------------------------------------------
__global__ void init_kernel() {
    int idx = blockIdx.x * blockDim.x + threadIdx.x;
    int stride = gridDim.x * blockDim.x;
    for (int i = idx; i < BATCH * RES; i += stride) g_V[i] = 0.0f;
}

// split+transpose W: g_W3[s][n][k] = bf16 split s of W[k][n]
__global__ void split_kernel(const float* __restrict__ W) {
    __shared__ float sh[32][33];
    const int k0 = blockIdx.x * 32;
    const int n0 = blockIdx.y * 32;
    const int tx = threadIdx.x;
    const int ty = threadIdx.y;
    #pragma unroll
    for (int i = ty; i < 32; i += 8)
        sh[i][tx] = W[(size_t)(k0 + i) * RES + n0 + tx];
    __syncthreads();
    #pragma unroll
    for (int i = ty; i < 32; i += 8) {
        float w = sh[tx][i];  // = W[k0+tx][n0+i]
        __nv_bfloat16 b0 = __float2bfloat16(w);
        float r1 = w - __bfloat162float(b0);
        __nv_bfloat16 b1 = __float2bfloat16(r1);
        float r2 = r1 - __bfloat162float(b1);
        __nv_bfloat16 b2 = __float2bfloat16(r2);
        size_t o = (size_t)(n0 + i) * RES + k0 + tx;
        g_W3[o]                         = b0;
        g_W3[(size_t)RES * RES + o]     = b1;
        g_W3[(size_t)2 * RES * RES + o] = b2;
    }
}

// ---------------------------------------------------------------------------
// step: Y = S_{t-1} @ (W0+W1+W2) via mma.sync bf16, fused LIF epilogue.
// ---------------------------------------------------------------------------
__global__ void __launch_bounds__(256, 1)
step_kernel(const float* __restrict__ x,
            const float* __restrict__ Win,
            float* __restrict__ out,
            int t)
{
    extern __shared__ __align__(128) char dsm[];
    __shared__ float sWin[BN * 3];

    const int tid  = threadIdx.x;
    const int lane = tid & 31;
    const int warp = tid >> 5;
    const int n0 = blockIdx.x * BN;
    const int m0 = blockIdx.y * BM;
    const int wm = warp >> 2;        // 0..1 -> m offset *32
    const int wn = warp & 3;         // 0..3 -> n offset *16
    const int grp  = lane >> 3;      // ldmatrix address group
    const int lrow = lane & 7;
    const int lr = lane >> 2;        // mma frag row
    const int lc = lane & 3;         // mma frag col pair

    for (int i = tid; i < BN * 3; i += 256) sWin[i] = Win[n0 * 3 + i];

    float acc[2][2][4];
    #pragma unroll
    for (int a = 0; a < 2; a++)
        #pragma unroll
        for (int b = 0; b < 2; b++)
            #pragma unroll
            for (int c = 0; c < 4; c++) acc[a][b][c] = 0.0f;

    if (t > 0) {
        const uint32_t sb = smem_u32(dsm);
        const char* gA = (const char*)g_S
            + (size_t)((t + 1) & 1) * BATCH * RES * 2 + (size_t)m0 * ROW_BYTES;
        const char* gB = (const char*)g_W3 + (size_t)n0 * ROW_BYTES;
        const size_t SSTR = (size_t)RES * RES * 2;   // split stride (bytes)

        // preload chunks 0..2 into stages 0..2
        #pragma unroll
        for (int c = 0; c < NSTAGE - 1; c++) {
            load_chunk(sb + c * STAGE_BYTES, gA, gB, c, SSTR);
            CP_COMMIT();
        }

        // ldmatrix per-thread row bases
        // A frag (mi): row = wm*32 + mi*16 + (grp&1)*8 + lrow ; k-half = grp>>1
        // B frag:      row = wn*16 + (grp>>1)*8 + lrow        ; k-half = grp&1
        const int rowA0 = wm * 32 + (grp & 1) * 8 + lrow;
        const int rowA1 = rowA0 + 16;
        const int rowB  = wn * 16 + (grp >> 1) * 8 + lrow;
        const uint32_t aOff0 = rowA0 * 128, aOff1 = rowA1 * 128, bOff = rowB * 128;
        const int a7_0 = rowA0 & 7, a7_1 = rowA1 & 7, b7 = rowB & 7;
        const int akh = grp >> 1, bkh = grp & 1;

        #pragma unroll 1
        for (int c = 0; c < KCHUNKS; c++) {
            CP_WAIT2();
            __syncthreads();

            const uint32_t aT = sb + (c & (NSTAGE - 1)) * STAGE_BYTES;
            const uint32_t bT = aT + 8192;

            #pragma unroll
            for (int kk = 0; kk < 4; kk++) {
                uint32_t a0[4], a1[4];
                ldsm4(a0, aT + aOff0 + ((((kk << 1) | akh) ^ a7_0) << 4));
                ldsm4(a1, aT + aOff1 + ((((kk << 1) | akh) ^ a7_1) << 4));
                #pragma unroll
                for (int s = 0; s < NSPLIT; s++) {
                    uint32_t bb[4];
                    ldsm4(bb, bT + s * 8192 + bOff + ((((kk << 1) | bkh) ^ b7) << 4));
                    // bb: {b0(nt0), b1(nt0), b0(nt1), b1(nt1)}
                    mma16816(acc[0][0], a0, bb[0], bb[1]);
                    mma16816(acc[0][1], a0, bb[2], bb[3]);
                    mma16816(acc[1][0], a1, bb[0], bb[1]);
                    mma16816(acc[1][1], a1, bb[2], bb[3]);
                }
            }

            // prefetch chunk c+3 into the stage last read at chunk c-1
            // (all warps passed that read at this iteration's barrier)
            const int cn = c + NSTAGE - 1;
            if (cn < KCHUNKS)
                load_chunk(sb + (cn & (NSTAGE - 1)) * STAGE_BYTES, gA, gB, cn, SSTR);
            CP_COMMIT();  // commit (possibly empty) to keep group counting uniform
        }
    }

    __syncthreads();

    // ---- fused LIF epilogue ----
    const float* xt = x + (size_t)t * BATCH * 3;
    float*         outT = out + (size_t)t * BATCH * RES;
    __nv_bfloat16* Sw   = g_S + (size_t)(t & 1) * BATCH * RES;

    #pragma unroll
    for (int mi = 0; mi < 2; mi++) {
        #pragma unroll
        for (int r = 0; r < 2; r++) {
            const int b = m0 + wm * 32 + mi * 16 + r * 8 + lr;
            const float x0 = xt[b * 3 + 0];
            const float x1 = xt[b * 3 + 1];
            const float x2 = xt[b * 3 + 2];
            #pragma unroll
            for (int nt = 0; nt < 2; nt++) {
                const int nl = wn * 16 + nt * 8 + lc * 2;
                const size_t vi = (size_t)b * RES + n0 + nl;
                const float inj0 = x0 * sWin[nl * 3 + 0] + x1 * sWin[nl * 3 + 1] + x2 * sWin[nl * 3 + 2];
                const float inj1 = x0 * sWin[nl * 3 + 3] + x1 * sWin[nl * 3 + 4] + x2 * sWin[nl * 3 + 5];
                float2 v = *(float2*)&g_V[vi];
                const float y0 = BETA * v.x + inj0 + acc[mi][nt][r * 2 + 0];
                const float y1 = BETA * v.y + inj1 + acc[mi][nt][r * 2 + 1];
                const float s0 = (y0 >= THRESH) ? 1.0f : 0.0f;
                const float s1 = (y1 >= THRESH) ? 1.0f : 0.0f;
                v.x = (y0 >= THRESH) ? 0.0f : y0;
                v.y = (y1 >= THRESH) ? 0.0f : y1;
                *(float2*)&g_V[vi] = v;
                float2 sp; sp.x = s0; sp.y = s1;
                *(float2*)&outT[vi] = sp;
                __nv_bfloat162 sb2;
                sb2.x = __float2bfloat16(s0);
                sb2.y = __float2bfloat16(s1);
                *(__nv_bfloat162*)&Sw[vi] = sb2;
            }
        }
    }
}

// ---------------------------------------------------------------------------
__global__ void __launch_bounds__(256)
logits_kernel(const float* __restrict__ spk,
              const float* __restrict__ Wout,
              float* __restrict__ logits)
{
    const int b = blockIdx.x;
    const int tid = threadIdx.x;
    float p0 = 0.0f, p1 = 0.0f;
    for (int r = tid; r < RES; r += 256) {
        float s = 0.0f;
        #pragma unroll
        for (int tt = 0; tt < 10; tt++)
            s += spk[((size_t)(T_STEPS - 10 + tt) * BATCH + b) * RES + r];
        s *= 0.1f;
        p0 = fmaf(s, Wout[r], p0);
        p1 = fmaf(s, Wout[RES + r], p1);
    }
    __shared__ float sh0[256];
    __shared__ float sh1[256];
    sh0[tid] = p0; sh1[tid] = p1;
    __syncthreads();
    for (int off = 128; off > 0; off >>= 1) {
        if (tid < off) { sh0[tid] += sh0[tid + off]; sh1[tid] += sh1[tid + off]; }
        __syncthreads();
    }
    if (tid == 0) {
        logits[b * OUTD + 0] = sh0[0];
        logits[b * OUTD + 1] = sh1[0];
    }
}

// ---------------------------------------------------------------------------
extern "C" void kernel_launch(void* const* d_in, const int* in_sizes, int n_in,
                              void* d_out, int out_size)
{
    const float* x    = (const float*)d_in[0];  // [200, 256, 3]
    const float* W    = (const float*)d_in[1];  // [2048, 2048]
    const float* Win  = (const float*)d_in[2];  // [2048, 3]
    const float* Wout = (const float*)d_in[3];  // [2, 2048]
    float* out = (float*)d_out;                 // spk [200*256*2048] | logits [256*2]

    cudaFuncSetAttribute(step_kernel, cudaFuncAttributeMaxDynamicSharedMemorySize, SMEM_DYN);

    init_kernel<<<512, 256>>>();
    split_kernel<<<dim3(RES / 32, RES / 32), dim3(32, 8)>>>(W);

    dim3 grid(RES / BN, BATCH / BM);  // (32, 4) = 128 CTAs
    for (int t = 0; t < T_STEPS; t++) {
        step_kernel<<<grid, 256, SMEM_DYN>>>(x, Win, out, t);
    }

    logits_kernel<<<BATCH, 256>>>(out, Wout, out + SPK_ELEMS);
}